// round 8
// baseline (speedup 1.0000x reference)
#include <cuda_runtime.h>
#include <cuda_bf16.h>
#include <cstdint>

#define L_ 128
#define B_ 4096
#define D_ 300
#define T_ (L_*B_)          // 524288 tokens
#define KK 304              // K rows (19 ksteps of 16)
#define NP 320              // Ws row length (N), cols 300..319 zero
#define NH 160              // N cols per CTA half
#define WR2 168             // W smem row stride (bf16)
#define SR2 312             // S smem row stride (bf16)
#define MT 64               // tokens per b-chunk

// smem layout (bytes)
#define SMEM_W  0           // 304*168*2 = 102144
#define SMEM_S0 102144      // 64*312*2  = 39936
#define SMEM_S1 142080      // 39936
#define SMEM_PQ 182016      // 4*64*4 = 1024
#define SMEM_PC 183040      // 1024
#define SMEM_TOTAL 184064

__device__ __nv_bfloat16 g_Wsb[KK*NP];  // symmetrized bf16 [k][n]
__device__ float g_q2[2*T_];            // per-N-half partial of s^T Ws s
__device__ float g_c2[2*T_];            // per-N-half partial of s_{l+1}^T Ws s_l

__device__ __forceinline__ void cp16(void* smem_dst, const void* gsrc){
    unsigned sa = (unsigned)__cvta_generic_to_shared(smem_dst);
    asm volatile("cp.async.cg.shared.global [%0], [%1], 16;" :: "r"(sa), "l"(gsrc));
}
__device__ __forceinline__ void ldmA4(unsigned& r0, unsigned& r1, unsigned& r2, unsigned& r3, const void* p){
    unsigned a = (unsigned)__cvta_generic_to_shared(p);
    asm volatile("ldmatrix.sync.aligned.m8n8.x4.shared.b16 {%0,%1,%2,%3},[%4];"
                 : "=r"(r0),"=r"(r1),"=r"(r2),"=r"(r3) : "r"(a));
}
__device__ __forceinline__ void ldmBT4(unsigned& r0, unsigned& r1, unsigned& r2, unsigned& r3, const void* p){
    unsigned a = (unsigned)__cvta_generic_to_shared(p);
    asm volatile("ldmatrix.sync.aligned.m8n8.x4.trans.shared.b16 {%0,%1,%2,%3},[%4];"
                 : "=r"(r0),"=r"(r1),"=r"(r2),"=r"(r3) : "r"(a));
}
__device__ __forceinline__ void ldmBT2(unsigned& r0, unsigned& r1, const void* p){
    unsigned a = (unsigned)__cvta_generic_to_shared(p);
    asm volatile("ldmatrix.sync.aligned.m8n8.x2.trans.shared.b16 {%0,%1},[%2];"
                 : "=r"(r0),"=r"(r1) : "r"(a));
}

// ---------------- pass 0: Wsb = bf16((W + W^T)/2), [KK][NP] ----------------
__global__ void pass0_symW(const float* __restrict__ W){
    int idx = blockIdx.x * blockDim.x + threadIdx.x;
    if (idx >= KK*NP) return;
    int d = idx / NP, e = idx % NP;
    float v = 0.f;
    if (d < D_ && e < D_) v = 0.5f * (W[d*D_ + e] + W[e*D_ + d]);
    g_Wsb[idx] = __float2bfloat16(v);
}

// ---------------- pass 1: persistent fused GEMM + dots ----------------
__global__ __launch_bounds__(512, 1)
void pass1_scores(const float* __restrict__ sent){
    extern __shared__ __align__(16) unsigned char smraw[];
    __nv_bfloat16* sW  = (__nv_bfloat16*)(smraw + SMEM_W);
    __nv_bfloat16* sS0 = (__nv_bfloat16*)(smraw + SMEM_S0);
    __nv_bfloat16* sS1 = (__nv_bfloat16*)(smraw + SMEM_S1);
    float* sPQ = (float*)(smraw + SMEM_PQ);   // [4][64]
    float* sPC = (float*)(smraw + SMEM_PC);   // [4][64]

    const int tid  = threadIdx.x;
    const int warp = tid >> 5, lane = tid & 31;
    const int g = lane >> 2, t4 = lane & 3;
    const int wm = warp >> 2, wn = warp & 3;        // 4M x 4N warp grid
    const int nh = blockIdx.x & 1;                  // N half
    const int bc = blockIdx.x >> 1;                 // b-chunk
    const long base = (long)bc * MT;

    const int rF = (lane & 7) + ((lane >> 3) & 1) * 8;
    const int cF = (lane >> 4) * 8;

    // stage resident W half
    for (int i = tid; i < KK*20; i += 512){
        int k = i / 20, c = (i % 20) * 8;
        cp16(sW + k*WR2 + c, g_Wsb + k*NP + nh*NH + c);
    }
    asm volatile("cp.async.commit_group;" ::: "memory");

    // stage S tiles for l=0 (S0) and l=1 (S1)
    #pragma unroll
    for (int lb = 0; lb < 2; lb++){
        __nv_bfloat16* dst = lb ? sS1 : sS0;
        for (int i = tid; i < MT*38; i += 512){
            int row = i / 38, col = (i % 38) * 8;
            __nv_bfloat16* p = dst + row*SR2 + col;
            const float* sp = sent + ((size_t)lb*B_ + base + row)*D_ + col;
            if (col + 8 <= D_){
                float4 a = *(const float4*)sp, b = *(const float4*)(sp + 4);
                p[0]=__float2bfloat16(a.x); p[1]=__float2bfloat16(a.y);
                p[2]=__float2bfloat16(a.z); p[3]=__float2bfloat16(a.w);
                p[4]=__float2bfloat16(b.x); p[5]=__float2bfloat16(b.y);
                p[6]=__float2bfloat16(b.z); p[7]=__float2bfloat16(b.w);
            } else {
                #pragma unroll
                for (int j = 0; j < 8; j++)
                    p[j] = (col + j < D_) ? __float2bfloat16(sp[j]) : __float2bfloat16(0.f);
            }
        }
    }
    asm volatile("cp.async.wait_group 0;" ::: "memory");
    __syncthreads();

    float4 pf[10];
    for (int l = 0; l < L_; l++){
        __nv_bfloat16* cur = (l & 1) ? sS1 : sS0;
        __nv_bfloat16* nxt = (l & 1) ? sS0 : sS1;
        const bool pfv = (l + 2 < L_);

        // 1. prefetch S_{l+2} (f32) into registers
        if (pfv){
            const float* srcb = sent + ((size_t)(l+2)*B_ + base)*D_;
            #pragma unroll
            for (int j = 0; j < 10; j++){
                int idx = tid + j*512;
                if (idx < MT*75){
                    int row = idx / 75, c4 = idx - row*75;
                    pf[j] = *(const float4*)(srcb + row*D_ + c4*4);
                }
            }
        }

        // 2. mma with 2-stage fragment software pipeline
        float acc[5][4];
        #pragma unroll
        for (int i=0;i<5;i++){ acc[i][0]=0.f; acc[i][1]=0.f; acc[i][2]=0.f; acc[i][3]=0.f; }

        unsigned fa[2][4], fb[2][5][2];
        // prologue: frags for ks=0
        ldmA4(fa[0][0],fa[0][1],fa[0][2],fa[0][3], cur + (wm*16 + rF)*SR2 + cF);
        {
            const __nv_bfloat16* wr = sW + rF*WR2 + wn*40;
            ldmBT4(fb[0][0][0],fb[0][0][1],fb[0][1][0],fb[0][1][1], wr + cF);
            ldmBT4(fb[0][2][0],fb[0][2][1],fb[0][3][0],fb[0][3][1], wr + 16 + cF);
            ldmBT2(fb[0][4][0],fb[0][4][1],                          wr + 32);
        }
        #pragma unroll
        for (int ks = 0; ks < 19; ks++){
            const int c0 = ks & 1, c1 = c0 ^ 1;
            if (ks < 18){
                ldmA4(fa[c1][0],fa[c1][1],fa[c1][2],fa[c1][3],
                      cur + (wm*16 + rF)*SR2 + (ks+1)*16 + cF);
                const __nv_bfloat16* wr = sW + ((ks+1)*16 + rF)*WR2 + wn*40;
                ldmBT4(fb[c1][0][0],fb[c1][0][1],fb[c1][1][0],fb[c1][1][1], wr + cF);
                ldmBT4(fb[c1][2][0],fb[c1][2][1],fb[c1][3][0],fb[c1][3][1], wr + 16 + cF);
                ldmBT2(fb[c1][4][0],fb[c1][4][1],                            wr + 32);
            }
            #pragma unroll
            for (int nf = 0; nf < 5; nf++)
                asm volatile(
                    "mma.sync.aligned.m16n8k16.row.col.f32.bf16.bf16.f32 "
                    "{%0,%1,%2,%3},{%4,%5,%6,%7},{%8,%9},{%0,%1,%2,%3};"
                    : "+f"(acc[nf][0]), "+f"(acc[nf][1]), "+f"(acc[nf][2]), "+f"(acc[nf][3])
                    : "r"(fa[c0][0]), "r"(fa[c0][1]), "r"(fa[c0][2]), "r"(fa[c0][3]),
                      "r"(fb[c0][nf][0]), "r"(fb[c0][nf][1]));
        }

        // 3. dots: q = z.s_l (cur), c = z.s_{l+1} (nxt)
        #pragma unroll
        for (int h = 0; h < 2; h++){
            const int row = wm*16 + h*8 + g;
            float pq = 0.f, pc = 0.f;
            #pragma unroll
            for (int nf = 0; nf < 5; nf++){
                int eg = nh*NH + wn*40 + nf*8 + 2*t4;
                if (eg < D_){
                    float z0 = acc[nf][h*2+0], z1 = acc[nf][h*2+1];
                    __nv_bfloat162 s2 = *(const __nv_bfloat162*)(cur + row*SR2 + eg);
                    pq += z0*__bfloat162float(s2.x) + z1*__bfloat162float(s2.y);
                    __nv_bfloat162 n2 = *(const __nv_bfloat162*)(nxt + row*SR2 + eg);
                    pc += z0*__bfloat162float(n2.x) + z1*__bfloat162float(n2.y);
                }
            }
            pq += __shfl_xor_sync(0xffffffffu, pq, 1);
            pq += __shfl_xor_sync(0xffffffffu, pq, 2);
            pc += __shfl_xor_sync(0xffffffffu, pc, 1);
            pc += __shfl_xor_sync(0xffffffffu, pc, 2);
            if (t4 == 0){ sPQ[wn*MT + row] = pq; sPC[wn*MT + row] = pc; }
        }
        __syncthreads();

        const size_t t0 = (size_t)l*B_ + base;
        if (tid < MT){
            g_q2[(size_t)nh*T_ + t0 + tid] = sPQ[tid] + sPQ[MT+tid] + sPQ[2*MT+tid] + sPQ[3*MT+tid];
        } else if (tid < 2*MT){
            int r = tid - MT;
            float v = (l < L_-1) ? (sPC[r] + sPC[MT+r] + sPC[2*MT+r] + sPC[3*MT+r]) : 0.f;
            g_c2[(size_t)nh*T_ + t0 + r] = v;
        }

        // 4. commit prefetched S_{l+2} into retiring buffer (cur)
        if (pfv){
            #pragma unroll
            for (int j = 0; j < 10; j++){
                int idx = tid + j*512;
                if (idx < MT*75){
                    int row = idx / 75, c4 = idx - row*75;
                    __nv_bfloat16* p = cur + row*SR2 + c4*4;
                    p[0]=__float2bfloat16(pf[j].x); p[1]=__float2bfloat16(pf[j].y);
                    p[2]=__float2bfloat16(pf[j].z); p[3]=__float2bfloat16(pf[j].w);
                }
            }
        }
        __syncthreads();
    }
}

// ---------------- pass 2: rolling-window softmax-combine (1 warp per batch col) ----------------
__global__ __launch_bounds__(256)
void pass2_combine(const float* __restrict__ sent, const int* __restrict__ size,
                   float* __restrict__ out){
    const int lane = threadIdx.x & 31;
    const int b = (blockIdx.x * blockDim.x + threadIdx.x) >> 5;
    if (b >= B_) return;
    const int sz = size[b];
    const float NEG = __int_as_float(0xff800000);
    const float INVD = 1.0f / (float)D_;
    const bool l3 = (lane < 11);

    const float4 Z4 = make_float4(0.f,0.f,0.f,0.f);
    float4 p0=Z4,p1=Z4,p2=Z4, c0,c1,c2, n0=Z4,n1=Z4,n2=Z4;

    const float4* row0 = (const float4*)(sent + (size_t)b * D_);
    c0 = row0[lane]; c1 = row0[lane+32]; c2 = l3 ? row0[lane+64] : Z4;
    const float4* row1 = (const float4*)(sent + (size_t)(B_ + b) * D_);
    n0 = row1[lane]; n1 = row1[lane+32]; n2 = l3 ? row1[lane+64] : Z4;

    float c_prev = 0.f;
    for (int l = 0; l < L_; l++){
        const int t = l*B_ + b;
        float c_cur = g_c2[t] + g_c2[T_ + t];
        float qv    = g_q2[t] + g_q2[T_ + t];
        float l1 = qv * INVD;
        float l0 = (l >= 1   && l < sz    ) ? c_prev * INVD : NEG;
        float l2 = (l < L_-1 && l < sz - 1) ? c_cur  * INVD : NEG;
        float m  = fmaxf(l1, fmaxf(l0, l2));
        float e0 = __expf(l0 - m), e1 = __expf(l1 - m), e2 = __expf(l2 - m);
        float inv = 1.0f / (e0 + e1 + e2);
        float w0 = e0 * inv, w1 = e1 * inv, w2 = e2 * inv;

        float4* o = (float4*)(out + (size_t)t * D_);
        float4 v;
        v.x = w1*c0.x + w0*p0.x + w2*n0.x;
        v.y = w1*c0.y + w0*p0.y + w2*n0.y;
        v.z = w1*c0.z + w0*p0.z + w2*n0.z;
        v.w = w1*c0.w + w0*p0.w + w2*n0.w;
        o[lane] = v;
        v.x = w1*c1.x + w0*p1.x + w2*n1.x;
        v.y = w1*c1.y + w0*p1.y + w2*n1.y;
        v.z = w1*c1.z + w0*p1.z + w2*n1.z;
        v.w = w1*c1.w + w0*p1.w + w2*n1.w;
        o[lane+32] = v;
        if (l3){
            v.x = w1*c2.x + w0*p2.x + w2*n2.x;
            v.y = w1*c2.y + w0*p2.y + w2*n2.y;
            v.z = w1*c2.z + w0*p2.z + w2*n2.z;
            v.w = w1*c2.w + w0*p2.w + w2*n2.w;
            o[lane+64] = v;
        }
        p0=c0; p1=c1; p2=c2;
        c0=n0; c1=n1; c2=n2;
        if (l + 2 < L_){
            const float4* rn = (const float4*)(sent + (size_t)((l+2)*B_ + b) * D_);
            n0 = rn[lane]; n1 = rn[lane+32]; n2 = l3 ? rn[lane+64] : Z4;
        } else {
            n0=Z4; n1=Z4; n2=Z4;
        }
        c_prev = c_cur;
    }
}

// dummy launch so ncu's "-s 5 -c 1" window (launch index 5) lands on
// pass1 of the second kernel_launch call: per call = pass0(0) pass1(1) pass2(2) dummy(3)
__global__ void pass3_nop(){}

extern "C" void kernel_launch(void* const* d_in, const int* in_sizes, int n_in,
                              void* d_out, int out_size){
    const float* sent = nullptr;
    const int*   size = nullptr;
    const float* W    = nullptr;
    for (int i = 0; i < n_in; i++){
        if      (in_sizes[i] == L_*B_*D_) sent = (const float*)d_in[i];
        else if (in_sizes[i] == B_)       size = (const int*)d_in[i];
        else if (in_sizes[i] == D_*D_)    W    = (const float*)d_in[i];
    }
    float* out = (float*)d_out;

    cudaFuncSetAttribute(pass1_scores, cudaFuncAttributeMaxDynamicSharedMemorySize, SMEM_TOTAL);

    pass0_symW<<<(KK*NP + 255)/256, 256>>>(W);
    pass1_scores<<<128, 512, SMEM_TOTAL>>>(sent);
    pass2_combine<<<(B_*32)/256, 256>>>(sent, size, out);
    pass3_nop<<<1, 32>>>();
}

// round 9
// speedup vs baseline: 1.0138x; 1.0138x over previous
#include <cuda_runtime.h>
#include <cuda_fp16.h>
#include <cstdint>

#define L_ 128
#define B_ 4096
#define D_ 300
#define T_ (L_*B_)          // 524288 tokens
#define KK 304              // K rows (19 ksteps of 16)
#define NP 320              // Ws row length (N), cols 300..319 zero
#define NH 160              // N cols per CTA half
#define WR2 168             // W smem row stride (f16)
#define SR2 312             // S smem row stride (f16)
#define MT 64               // tokens per b-chunk

// smem layout (bytes)
#define SMEM_W  0           // 304*168*2 = 102144
#define SMEM_S0 102144      // 64*312*2  = 39936
#define SMEM_S1 142080      // 39936
#define SMEM_PQ 182016      // 4*64*4 = 1024
#define SMEM_PC 183040      // 1024
#define SMEM_TOTAL 184064

__device__ __half g_Wsh[KK*NP];         // symmetrized f16 [k][n]
__device__ float g_q2[2*T_];            // per-N-half partial of s^T Ws s
__device__ float g_c2[2*T_];            // per-N-half partial of s_{l+1}^T Ws s_l

__device__ __forceinline__ void cp16(void* smem_dst, const void* gsrc){
    unsigned sa = (unsigned)__cvta_generic_to_shared(smem_dst);
    asm volatile("cp.async.cg.shared.global [%0], [%1], 16;" :: "r"(sa), "l"(gsrc));
}
__device__ __forceinline__ void ldmA4(unsigned& r0, unsigned& r1, unsigned& r2, unsigned& r3, const void* p){
    unsigned a = (unsigned)__cvta_generic_to_shared(p);
    asm volatile("ldmatrix.sync.aligned.m8n8.x4.shared.b16 {%0,%1,%2,%3},[%4];"
                 : "=r"(r0),"=r"(r1),"=r"(r2),"=r"(r3) : "r"(a));
}
__device__ __forceinline__ void ldmBT4(unsigned& r0, unsigned& r1, unsigned& r2, unsigned& r3, const void* p){
    unsigned a = (unsigned)__cvta_generic_to_shared(p);
    asm volatile("ldmatrix.sync.aligned.m8n8.x4.trans.shared.b16 {%0,%1,%2,%3},[%4];"
                 : "=r"(r0),"=r"(r1),"=r"(r2),"=r"(r3) : "r"(a));
}
__device__ __forceinline__ void ldmBT2(unsigned& r0, unsigned& r1, const void* p){
    unsigned a = (unsigned)__cvta_generic_to_shared(p);
    asm volatile("ldmatrix.sync.aligned.m8n8.x2.trans.shared.b16 {%0,%1},[%2];"
                 : "=r"(r0),"=r"(r1) : "r"(a));
}

// ---------------- pass 0: Wsh = f16((W + W^T)/2), [KK][NP] ----------------
__global__ void pass0_symW(const float* __restrict__ W){
    int idx = blockIdx.x * blockDim.x + threadIdx.x;
    if (idx >= KK*NP) return;
    int d = idx / NP, e = idx % NP;
    float v = 0.f;
    if (d < D_ && e < D_) v = 0.5f * (W[d*D_ + e] + W[e*D_ + d]);
    g_Wsh[idx] = __float2half(v);
}

// ---------------- pass 1: persistent fused GEMM (f16 acc) + dots ----------------
__global__ __launch_bounds__(512, 1)
void pass1_scores(const float* __restrict__ sent){
    extern __shared__ __align__(16) unsigned char smraw[];
    __half* sW  = (__half*)(smraw + SMEM_W);
    __half* sS0 = (__half*)(smraw + SMEM_S0);
    __half* sS1 = (__half*)(smraw + SMEM_S1);
    float* sPQ = (float*)(smraw + SMEM_PQ);   // [4][64]
    float* sPC = (float*)(smraw + SMEM_PC);   // [4][64]

    const int tid  = threadIdx.x;
    const int warp = tid >> 5, lane = tid & 31;
    const int g = lane >> 2, t4 = lane & 3;
    const int wm = warp >> 2, wn = warp & 3;        // 4M x 4N warp grid
    const int nh = blockIdx.x & 1;                  // N half
    const int bc = blockIdx.x >> 1;                 // b-chunk
    const long base = (long)bc * MT;

    const int rF = (lane & 7) + ((lane >> 3) & 1) * 8;
    const int cF = (lane >> 4) * 8;

    // stage resident W half
    for (int i = tid; i < KK*20; i += 512){
        int k = i / 20, c = (i % 20) * 8;
        cp16(sW + k*WR2 + c, g_Wsh + k*NP + nh*NH + c);
    }
    asm volatile("cp.async.commit_group;" ::: "memory");

    // stage S tiles for l=0 (S0) and l=1 (S1)
    #pragma unroll
    for (int lb = 0; lb < 2; lb++){
        __half* dst = lb ? sS1 : sS0;
        for (int i = tid; i < MT*38; i += 512){
            int row = i / 38, col = (i % 38) * 8;
            __half* p = dst + row*SR2 + col;
            const float* sp = sent + ((size_t)lb*B_ + base + row)*D_ + col;
            if (col + 8 <= D_){
                float4 a = *(const float4*)sp, b = *(const float4*)(sp + 4);
                p[0]=__float2half(a.x); p[1]=__float2half(a.y);
                p[2]=__float2half(a.z); p[3]=__float2half(a.w);
                p[4]=__float2half(b.x); p[5]=__float2half(b.y);
                p[6]=__float2half(b.z); p[7]=__float2half(b.w);
            } else {
                #pragma unroll
                for (int j = 0; j < 8; j++)
                    p[j] = (col + j < D_) ? __float2half(sp[j]) : __float2half(0.f);
            }
        }
    }
    asm volatile("cp.async.wait_group 0;" ::: "memory");
    __syncthreads();

    float4 pf[10];
    for (int l = 0; l < L_; l++){
        __half* cur = (l & 1) ? sS1 : sS0;
        __half* nxt = (l & 1) ? sS0 : sS1;
        const bool pfv = (l + 2 < L_);

        // 1. prefetch S_{l+2} (f32) into registers
        if (pfv){
            const float* srcb = sent + ((size_t)(l+2)*B_ + base)*D_;
            #pragma unroll
            for (int j = 0; j < 10; j++){
                int idx = tid + j*512;
                if (idx < MT*75){
                    int row = idx / 75, c4 = idx - row*75;
                    pf[j] = *(const float4*)(srcb + row*D_ + c4*4);
                }
            }
        }

        // 2. mma, f16 accumulate: acc[nf] = {d0,d1} packed half2
        unsigned acc[5][2];
        #pragma unroll
        for (int i=0;i<5;i++){ acc[i][0]=0u; acc[i][1]=0u; }
        #pragma unroll
        for (int ks = 0; ks < 19; ks++){
            unsigned a0,a1,a2,a3;
            ldmA4(a0,a1,a2,a3, cur + (wm*16 + rF)*SR2 + ks*16 + cF);
            const __half* wr = sW + (ks*16 + rF)*WR2 + wn*40;
            unsigned b[5][2];
            ldmBT4(b[0][0],b[0][1],b[1][0],b[1][1], wr + cF);
            ldmBT4(b[2][0],b[2][1],b[3][0],b[3][1], wr + 16 + cF);
            ldmBT2(b[4][0],b[4][1],                 wr + 32);
            #pragma unroll
            for (int nf = 0; nf < 5; nf++)
                asm volatile(
                    "mma.sync.aligned.m16n8k16.row.col.f16.f16.f16.f16 "
                    "{%0,%1},{%2,%3,%4,%5},{%6,%7},{%0,%1};"
                    : "+r"(acc[nf][0]), "+r"(acc[nf][1])
                    : "r"(a0), "r"(a1), "r"(a2), "r"(a3),
                      "r"(b[nf][0]), "r"(b[nf][1]));
        }

        // 3. dots: q = z.s_l (cur), c = z.s_{l+1} (nxt)   [fp32]
        #pragma unroll
        for (int h = 0; h < 2; h++){
            const int row = wm*16 + h*8 + g;
            float pq = 0.f, pc = 0.f;
            #pragma unroll
            for (int nf = 0; nf < 5; nf++){
                int eg = nh*NH + wn*40 + nf*8 + 2*t4;
                if (eg < D_){
                    float2 z = __half22float2(*(__half2*)&acc[nf][h]);
                    __half2 s2 = *(const __half2*)(cur + row*SR2 + eg);
                    float2 sf = __half22float2(s2);
                    pq += z.x*sf.x + z.y*sf.y;
                    __half2 n2 = *(const __half2*)(nxt + row*SR2 + eg);
                    float2 nf2 = __half22float2(n2);
                    pc += z.x*nf2.x + z.y*nf2.y;
                }
            }
            pq += __shfl_xor_sync(0xffffffffu, pq, 1);
            pq += __shfl_xor_sync(0xffffffffu, pq, 2);
            pc += __shfl_xor_sync(0xffffffffu, pc, 1);
            pc += __shfl_xor_sync(0xffffffffu, pc, 2);
            if (t4 == 0){ sPQ[wn*MT + row] = pq; sPC[wn*MT + row] = pc; }
        }
        __syncthreads();

        const size_t t0 = (size_t)l*B_ + base;
        if (tid < MT){
            g_q2[(size_t)nh*T_ + t0 + tid] = sPQ[tid] + sPQ[MT+tid] + sPQ[2*MT+tid] + sPQ[3*MT+tid];
        } else if (tid < 2*MT){
            int r = tid - MT;
            float v = (l < L_-1) ? (sPC[r] + sPC[MT+r] + sPC[2*MT+r] + sPC[3*MT+r]) : 0.f;
            g_c2[(size_t)nh*T_ + t0 + r] = v;
        }

        // 4. commit prefetched S_{l+2} into retiring buffer (cur)
        if (pfv){
            #pragma unroll
            for (int j = 0; j < 10; j++){
                int idx = tid + j*512;
                if (idx < MT*75){
                    int row = idx / 75, c4 = idx - row*75;
                    __half* p = cur + row*SR2 + c4*4;
                    p[0]=__float2half(pf[j].x); p[1]=__float2half(pf[j].y);
                    p[2]=__float2half(pf[j].z); p[3]=__float2half(pf[j].w);
                }
            }
        }
        __syncthreads();
    }
}

// ---------------- pass 2: rolling-window softmax-combine (1 warp per batch col) ----------------
__global__ __launch_bounds__(256)
void pass2_combine(const float* __restrict__ sent, const int* __restrict__ size,
                   float* __restrict__ out){
    const int lane = threadIdx.x & 31;
    const int b = (blockIdx.x * blockDim.x + threadIdx.x) >> 5;
    if (b >= B_) return;
    const int sz = size[b];
    const float NEG = __int_as_float(0xff800000);
    const float INVD = 1.0f / (float)D_;
    const bool l3 = (lane < 11);

    const float4 Z4 = make_float4(0.f,0.f,0.f,0.f);
    float4 p0=Z4,p1=Z4,p2=Z4, c0,c1,c2, n0=Z4,n1=Z4,n2=Z4;

    const float4* row0 = (const float4*)(sent + (size_t)b * D_);
    c0 = row0[lane]; c1 = row0[lane+32]; c2 = l3 ? row0[lane+64] : Z4;
    const float4* row1 = (const float4*)(sent + (size_t)(B_ + b) * D_);
    n0 = row1[lane]; n1 = row1[lane+32]; n2 = l3 ? row1[lane+64] : Z4;

    float c_prev = 0.f;
    for (int l = 0; l < L_; l++){
        const int t = l*B_ + b;
        float c_cur = g_c2[t] + g_c2[T_ + t];
        float qv    = g_q2[t] + g_q2[T_ + t];
        float l1 = qv * INVD;
        float l0 = (l >= 1   && l < sz    ) ? c_prev * INVD : NEG;
        float l2 = (l < L_-1 && l < sz - 1) ? c_cur  * INVD : NEG;
        float m  = fmaxf(l1, fmaxf(l0, l2));
        float e0 = __expf(l0 - m), e1 = __expf(l1 - m), e2 = __expf(l2 - m);
        float inv = 1.0f / (e0 + e1 + e2);
        float w0 = e0 * inv, w1 = e1 * inv, w2 = e2 * inv;

        float4* o = (float4*)(out + (size_t)t * D_);
        float4 v;
        v.x = w1*c0.x + w0*p0.x + w2*n0.x;
        v.y = w1*c0.y + w0*p0.y + w2*n0.y;
        v.z = w1*c0.z + w0*p0.z + w2*n0.z;
        v.w = w1*c0.w + w0*p0.w + w2*n0.w;
        o[lane] = v;
        v.x = w1*c1.x + w0*p1.x + w2*n1.x;
        v.y = w1*c1.y + w0*p1.y + w2*n1.y;
        v.z = w1*c1.z + w0*p1.z + w2*n1.z;
        v.w = w1*c1.w + w0*p1.w + w2*n1.w;
        o[lane+32] = v;
        if (l3){
            v.x = w1*c2.x + w0*p2.x + w2*n2.x;
            v.y = w1*c2.y + w0*p2.y + w2*n2.y;
            v.z = w1*c2.z + w0*p2.z + w2*n2.z;
            v.w = w1*c2.w + w0*p2.w + w2*n2.w;
            o[lane+64] = v;
        }
        p0=c0; p1=c1; p2=c2;
        c0=n0; c1=n1; c2=n2;
        if (l + 2 < L_){
            const float4* rn = (const float4*)(sent + (size_t)((l+2)*B_ + b) * D_);
            n0 = rn[lane]; n1 = rn[lane+32]; n2 = l3 ? rn[lane+64] : Z4;
        } else {
            n0=Z4; n1=Z4; n2=Z4;
        }
        c_prev = c_cur;
    }
}

extern "C" void kernel_launch(void* const* d_in, const int* in_sizes, int n_in,
                              void* d_out, int out_size){
    const float* sent = nullptr;
    const int*   size = nullptr;
    const float* W    = nullptr;
    for (int i = 0; i < n_in; i++){
        if      (in_sizes[i] == L_*B_*D_) sent = (const float*)d_in[i];
        else if (in_sizes[i] == B_)       size = (const int*)d_in[i];
        else if (in_sizes[i] == D_*D_)    W    = (const float*)d_in[i];
    }
    float* out = (float*)d_out;

    cudaFuncSetAttribute(pass1_scores, cudaFuncAttributeMaxDynamicSharedMemorySize, SMEM_TOTAL);

    pass0_symW<<<(KK*NP + 255)/256, 256>>>(W);
    pass1_scores<<<128, 512, SMEM_TOTAL>>>(sent);
    pass2_combine<<<(B_*32)/256, 256>>>(sent, size, out);
}